// round 13
// baseline (speedup 1.0000x reference)
#include <cuda_runtime.h>
#include <cuda_fp16.h>
#include <math.h>
#include <stdint.h>

#define M_BATCH 2048
#define N_OUT   4096
#define K_IN    4096
#define NCTA    296

// Persistent state (module-load allocations; no runtime alloc).
__device__ __half g_xh[(size_t)M_BATCH * K_IN];   // fp16(x)
__device__ __half g_wh[(size_t)N_OUT * K_IN];     // fp16(Wn)
__device__ float  g_coef[N_OUT];                  // exp(wls)/norm per row
__device__ unsigned g_sync;                       // monotonic grid-sync counter
__device__ unsigned g_wflag[32 * 64];             // epoch-tagged (ntblock, slab)

// ---------------------------------------------------------------------------
__device__ __forceinline__ uint32_t smem_u32(const void* p) {
    uint32_t a;
    asm("{ .reg .u64 t; cvta.to.shared.u64 t, %1; cvt.u32.u64 %0, t; }"
        : "=r"(a) : "l"(p));
    return a;
}
__device__ __forceinline__ void cp16(uint32_t s, const void* g) {
    asm volatile("cp.async.cg.shared.global [%0], [%1], 16;" :: "r"(s), "l"(g));
}
#define CP_COMMIT() asm volatile("cp.async.commit_group;" ::: "memory")
#define CP_WAIT1()  asm volatile("cp.async.wait_group 1;" ::: "memory")

#define LDM4(d, addr)                                                         \
    asm volatile("ldmatrix.sync.aligned.m8n8.x4.shared.b16 {%0,%1,%2,%3}, [%4];" \
        : "=r"((d)[0]), "=r"((d)[1]), "=r"((d)[2]), "=r"((d)[3]) : "r"(addr))

#define MMAF16(c, a, b0, b1)                                                  \
    asm volatile("mma.sync.aligned.m16n8k16.row.col.f32.f16.f16.f32 "         \
        "{%0,%1,%2,%3}, {%4,%5,%6,%7}, {%8,%9}, {%0,%1,%2,%3};"               \
        : "+f"((c)[0]), "+f"((c)[1]), "+f"((c)[2]), "+f"((c)[3])              \
        : "r"((a)[0]), "r"((a)[1]), "r"((a)[2]), "r"((a)[3]), "r"(b0), "r"(b1))

__device__ __forceinline__ uint32_t pack2(float a, float b) {
    __half2 h = __halves2half2(__float2half_rn(a), __float2half_rn(b));
    return *(uint32_t*)&h;
}

// ---------------------------------------------------------------------------
// Fused persistent kernel: prep + grid-sync + (W-convert || GEMM).
// 296 CTAs (2/SM, all co-resident), 128 threads.
// GEMM: CTA tile 128x128, 4 warps (64x64), BK=64, 3-stage cp.async,
// static flat schedule: slot s runs tile j=s, then j=591-s if 80<=s<=295.
// ---------------------------------------------------------------------------
#define STAGE 32768
#define NSTAGE 3
#define SMEM_TOTAL (NSTAGE * STAGE)

__global__ __launch_bounds__(128, 2)
void fused(const float* __restrict__ x, const float* __restrict__ W,
           const float* __restrict__ wls, const float* __restrict__ bias,
           float* __restrict__ y, float* __restrict__ jac) {
    extern __shared__ __align__(1024) char smem[];
    const uint32_t sb = smem_u32(smem);
    float* sred = (float*)smem;           // scratch during prep phases

    const int tid  = threadIdx.x;
    const int wid  = tid >> 5;
    const int lane = tid & 31;
    const int bidx = blockIdx.x;

    // ================= Phase 1a: x -> fp16 (grid-stride, 8 elems/iter) =====
    for (size_t g = (size_t)bidx * 128 + tid;
         g < (size_t)(M_BATCH * K_IN / 8); g += (size_t)NCTA * 128) {
        size_t i = g * 8;
        float4 a = *(const float4*)(x + i);
        float4 b = *(const float4*)(x + i + 4);
        uint4 out = { pack2(a.x, a.y), pack2(a.z, a.w),
                      pack2(b.x, b.y), pack2(b.z, b.w) };
        *(uint4*)(&g_xh[i]) = out;
    }

    // ================= Phase 1b: W row norms + coef + jac ==================
    for (int o = bidx; o < N_OUT; o += NCTA) {
        const int br = o >> 5, ncols = (br + 1) << 5, dstart = br << 5;
        const float* wrow = W + (size_t)o * K_IN;
        float ss = 0.f;
        for (int base = tid * 8; base < ncols; base += 1024) {
            float4 a = *(const float4*)(wrow + base);
            float4 b = *(const float4*)(wrow + base + 4);
            float w[8] = { a.x, a.y, a.z, a.w, b.x, b.y, b.z, b.w };
            #pragma unroll
            for (int e = 0; e < 8; e++) {
                float wm = (base + e >= dstart) ? expf(w[e]) : w[e];
                ss += wm * wm;
            }
        }
        #pragma unroll
        for (int off = 16; off; off >>= 1)
            ss += __shfl_xor_sync(0xffffffffu, ss, off);
        if (lane == 0) sred[wid] = ss;
        __syncthreads();
        if (tid == 0) {
            float s = sred[0] + sred[1] + sred[2] + sred[3];
            float norm = sqrtf(s);
            float lscale = wls[o];
            g_coef[o] = expf(lscale) / norm;
            sred[4] = lscale - logf(norm);
        }
        __syncthreads();
        if (tid < 32)
            jac[(size_t)o * 32 + tid] = sred[4] + wrow[dstart + tid];
        __syncthreads();
    }

    // ================= Grid sync (monotonic counter, replay-safe) ==========
    __threadfence();
    __syncthreads();
    if (tid == 0) {
        unsigned my = atomicAdd(&g_sync, 1u);
        unsigned ep = my / NCTA;
        unsigned tgt = (ep + 1u) * NCTA;
        while (*(volatile unsigned*)&g_sync < tgt) {}
        sred[0] = __uint_as_float(ep);
    }
    __syncthreads();
    const unsigned ftarget = __float_as_uint(sred[0]) + 1u;
    __syncthreads();

    // ================= Phase 2: W -> fp16 conversion jobs (flagged) ========
    // Job g: slab sl=g>>5 (64 cols), block-row nb=g&31 (128 rows).
    // Low slabs complete first across all nb (matches GEMM consumption).
    for (int g = bidx; g < 2048; g += NCTA) {
        const int sl = g >> 5, nb = g & 31;
        if (sl <= 2 * nb + 1) {
            const int o = (nb << 7) + tid;          // one row per thread
            const int br = o >> 5, ncols = (br + 1) << 5, dstart = br << 5;
            const float coef = g_coef[o];
            const int c0 = sl << 6;
            const float* wrow = W + (size_t)o * K_IN + c0;
            __half* dst = g_wh + (size_t)o * K_IN + c0;
            #pragma unroll
            for (int seg = 0; seg < 8; seg++) {
                const int cb = c0 + seg * 8;
                uint4 out;
                if (cb < ncols) {                   // 8|cb, 32|ncols => whole seg valid
                    float4 a = *(const float4*)(wrow + seg * 8);
                    float4 b = *(const float4*)(wrow + seg * 8 + 4);
                    float w[8] = { a.x, a.y, a.z, a.w, b.x, b.y, b.z, b.w };
                    float wn[8];
                    #pragma unroll
                    for (int e = 0; e < 8; e++) {
                        float wm = (cb + e >= dstart) ? expf(w[e]) : w[e];
                        wn[e] = coef * wm;
                    }
                    out = make_uint4(pack2(wn[0], wn[1]), pack2(wn[2], wn[3]),
                                     pack2(wn[4], wn[5]), pack2(wn[6], wn[7]));
                } else {
                    out = make_uint4(0u, 0u, 0u, 0u);  // zero-pad region
                }
                *(uint4*)(dst + seg * 8) = out;
            }
            __threadfence();
            __syncthreads();
            if (tid == 0)
                *(volatile unsigned*)&g_wflag[(nb << 6) + sl] = ftarget;
        }
    }

    // ================= Phase 3: persistent GEMM ============================
    const int wm = wid >> 1;          // 0..1
    const int wn = wid & 1;           // 0..1
    const int s = bidx;
    const int ntiles = (s >= 80) ? 2 : 1;

    int j = s;
    int nt = 31 - (j >> 4);
    int mt = j & 15;
    int n0 = nt << 7;
    int m0 = mt << 7;
    int NC = (nt + 1) << 1;

    const __half* gA = g_xh + (size_t)m0 * K_IN;
    const __half* gB = g_wh + (size_t)n0 * K_IN;

    auto gate = [&](int ntb, int c) {
        if (tid == 0) {
            volatile unsigned* f = (volatile unsigned*)&g_wflag[(ntb << 6) + c];
            while (*f < ftarget) {}
        }
    };

    auto load_stage = [&](int st, int c) {
        const uint32_t base = sb + st * STAGE;
        const int k0 = c << 6;
        #pragma unroll
        for (int i = 0; i < 8; i++) {
            const int idx = tid + (i << 7);
            const int r = idx >> 3;
            const int ch = idx & 7;
            const size_t go = (size_t)r * K_IN + k0 + (ch << 3);
            const uint32_t so = (uint32_t)((r << 7) | ((ch ^ (r & 7)) << 4));
            cp16(base + so,         gA + go);
            cp16(base + 16384 + so, gB + go);
        }
    };

    gate(nt, 0);
    gate(nt, 1);
    __syncthreads();
    load_stage(0, 0);
    CP_COMMIT();
    load_stage(1, 1);
    CP_COMMIT();

    for (int t = 0; t < ntiles; t++) {
        float acc[4][8][4];
        #pragma unroll
        for (int i = 0; i < 4; i++)
            #pragma unroll
            for (int jj = 0; jj < 8; jj++)
                #pragma unroll
                for (int k = 0; k < 4; k++) acc[i][jj][k] = 0.f;

        int st = 2;
        for (int c = 0; c < NC; ++c) {
            CP_WAIT1();
            if (c + 2 < NC) gate(nt, c + 2);
            __syncthreads();
            if (c + 2 < NC) load_stage(st, c + 2);
            CP_COMMIT();
            if (++st == NSTAGE) st = 0;

            const uint32_t base = sb + (c % NSTAGE) * STAGE;
            #pragma unroll
            for (int ks = 0; ks < 4; ks++) {
                uint32_t ah[4][4];
                #pragma unroll
                for (int mf = 0; mf < 4; mf++) {
                    const int row = (wm << 6) + (mf << 4) + (lane & 15);
                    const int ch = ((ks << 1) + (lane >> 4)) ^ (row & 7);
                    LDM4(ah[mf], base + (row << 7) + (ch << 4));
                }
                #pragma unroll
                for (int ng = 0; ng < 4; ng++) {
                    const int n = (wn << 6) + (ng << 4) + ((lane >> 4) << 3) + (lane & 7);
                    const int ch = ((ks << 1) + ((lane >> 3) & 1)) ^ (n & 7);
                    uint32_t bh[4];
                    LDM4(bh, base + 16384 + (n << 7) + (ch << 4));
                    #pragma unroll
                    for (int mf = 0; mf < 4; mf++)
                        #pragma unroll
                        for (int h = 0; h < 2; h++)
                            MMAF16(acc[mf][(ng << 1) + h], ah[mf], bh[2 * h], bh[2 * h + 1]);
                }
            }
        }

        const int m0_out = m0, n0_out = n0;

        __syncthreads();    // everyone done reading this tile's smem
        if (t + 1 < ntiles) {
            j = 591 - s;
            nt = 31 - (j >> 4);
            mt = j & 15;
            n0 = nt << 7;
            m0 = mt << 7;
            NC = (nt + 1) << 1;
            gA = g_xh + (size_t)m0 * K_IN;
            gB = g_wh + (size_t)n0 * K_IN;
            gate(nt, 0);
            gate(nt, 1);
            __syncthreads();
            load_stage(0, 0);
            CP_COMMIT();
            load_stage(1, 1);
            CP_COMMIT();
        }

        #pragma unroll
        for (int mf = 0; mf < 4; mf++) {
            const int r = m0_out + (wm << 6) + (mf << 4) + (lane >> 2);
            #pragma unroll
            for (int nf = 0; nf < 8; nf++) {
                const int cc = n0_out + (wn << 6) + (nf << 3) + ((lane & 3) << 1);
                const float b0 = __ldg(bias + cc);
                const float b1 = __ldg(bias + cc + 1);
                float2 v0 = { acc[mf][nf][0] + b0, acc[mf][nf][1] + b1 };
                float2 v1 = { acc[mf][nf][2] + b0, acc[mf][nf][3] + b1 };
                *(float2*)(y + (size_t)r * N_OUT + cc)       = v0;
                *(float2*)(y + (size_t)(r + 8) * N_OUT + cc) = v1;
            }
        }
    }
}

// ---------------------------------------------------------------------------
extern "C" void kernel_launch(void* const* d_in, const int* in_sizes, int n_in,
                              void* d_out, int out_size) {
    const float* x    = (const float*)d_in[0];
    const float* W    = (const float*)d_in[1];
    const float* bias = (const float*)d_in[2];
    const float* wls  = (const float*)d_in[3];
    // masks (d_in[4], d_in[5]) deterministic; never read.

    float* y   = (float*)d_out;
    float* jac = y + (size_t)M_BATCH * N_OUT;

    cudaFuncSetAttribute(fused, cudaFuncAttributeMaxDynamicSharedMemorySize,
                         SMEM_TOTAL);

    fused<<<NCTA, 128, SMEM_TOTAL>>>(x, W, wls, bias, y, jac);
}

// round 14
// speedup vs baseline: 1.4007x; 1.4007x over previous
#include <cuda_runtime.h>
#include <cuda_fp16.h>
#include <math.h>
#include <stdint.h>

#define M_BATCH 2048
#define N_OUT   4096
#define K_IN    4096

// Persistent fp16 operands (module-load allocations; no runtime alloc).
__device__ __half g_xh[(size_t)M_BATCH * K_IN];   // fp16(x)
__device__ __half g_wh[(size_t)N_OUT * K_IN];     // fp16(Wn)

// ---------------------------------------------------------------------------
__device__ __forceinline__ uint32_t smem_u32(const void* p) {
    uint32_t a;
    asm("{ .reg .u64 t; cvta.to.shared.u64 t, %1; cvt.u32.u64 %0, t; }"
        : "=r"(a) : "l"(p));
    return a;
}
__device__ __forceinline__ void cp16(uint32_t s, const void* g) {
    asm volatile("cp.async.cg.shared.global [%0], [%1], 16;" :: "r"(s), "l"(g));
}
#define CP_COMMIT() asm volatile("cp.async.commit_group;" ::: "memory")
#define CP_WAIT0()  asm volatile("cp.async.wait_group 0;" ::: "memory")

#define LDM4(d, addr)                                                         \
    asm volatile("ldmatrix.sync.aligned.m8n8.x4.shared.b16 {%0,%1,%2,%3}, [%4];" \
        : "=r"((d)[0]), "=r"((d)[1]), "=r"((d)[2]), "=r"((d)[3]) : "r"(addr))

#define MMAF16(c, a, b0, b1)                                                  \
    asm volatile("mma.sync.aligned.m16n8k16.row.col.f32.f16.f16.f32 "         \
        "{%0,%1,%2,%3}, {%4,%5,%6,%7}, {%8,%9}, {%0,%1,%2,%3};"               \
        : "+f"((c)[0]), "+f"((c)[1]), "+f"((c)[2]), "+f"((c)[3])              \
        : "r"((a)[0]), "r"((a)[1]), "r"((a)[2]), "r"((a)[3]), "r"(b0), "r"(b1))

__device__ __forceinline__ uint32_t pack2(float a, float b) {
    __half2 h = __halves2half2(__float2half_rn(a), __float2half_rn(b));
    return *(uint32_t*)&h;
}

// ---------------------------------------------------------------------------
// Merged prep (R12, proven): blocks [0,4096) W rows; [4096,8192) x slices.
// ---------------------------------------------------------------------------
__global__ void prep_all(const float* __restrict__ x,
                         const float* __restrict__ W,
                         const float* __restrict__ wls,
                         float* __restrict__ jac_out) {
    extern __shared__ float sh[];    // [4096] row cache + [256] reduction
    const int tid = threadIdx.x;
    if (blockIdx.x < 4096) {
        const int o = blockIdx.x;
        const int br = o >> 5;
        const int ncols = (br + 1) << 5;
        const int dstart = br << 5;
        const int kmax_tile = ((o >> 7) + 1) << 7;

        float* row = sh;
        float* red = sh + 4096;

        const float* wrow = W + (size_t)o * K_IN;
        __half* wh = g_wh + (size_t)o * K_IN;

        float ss = 0.f;
        for (int base = tid * 8; base < ncols; base += 2048) {
            float4 a = *(const float4*)(wrow + base);
            float4 b = *(const float4*)(wrow + base + 4);
            *(float4*)(row + base)     = a;
            *(float4*)(row + base + 4) = b;
            float w[8] = { a.x, a.y, a.z, a.w, b.x, b.y, b.z, b.w };
            #pragma unroll
            for (int e = 0; e < 8; e++) {
                float wm = (base + e >= dstart) ? expf(w[e]) : w[e];
                ss += wm * wm;
            }
        }
        red[tid] = ss;
        __syncthreads();
        #pragma unroll
        for (int s = 128; s > 0; s >>= 1) {
            if (tid < s) red[tid] += red[tid + s];
            __syncthreads();
        }
        const float norm   = sqrtf(red[0]);
        const float lscale = wls[o];
        const float coef   = expf(lscale) / norm;
        const float logn   = logf(norm);

        for (int base = tid * 8; base < ncols; base += 2048) {
            float wn[8];
            #pragma unroll
            for (int e = 0; e < 8; e++) {
                float w = row[base + e];
                float wm = (base + e >= dstart) ? expf(w) : w;
                wn[e] = coef * wm;
                if (base + e >= dstart)
                    jac_out[(size_t)o * 32 + (base + e - dstart)] =
                        lscale + w - logn;
            }
            uint4 out = { pack2(wn[0], wn[1]), pack2(wn[2], wn[3]),
                          pack2(wn[4], wn[5]), pack2(wn[6], wn[7]) };
            *(uint4*)(wh + base) = out;
        }
        const uint4 z4 = {0u, 0u, 0u, 0u};
        for (int base = ncols + tid * 8; base < kmax_tile; base += 2048)
            *(uint4*)(wh + base) = z4;
    } else {
        size_t i = ((size_t)(blockIdx.x - 4096) * blockDim.x + tid) * 8;
        float4 a = *(const float4*)(x + i);
        float4 b = *(const float4*)(x + i + 4);
        uint4 out = { pack2(a.x, a.y), pack2(a.z, a.w),
                      pack2(b.x, b.y), pack2(b.z, b.w) };
        *(uint4*)(&g_xh[i]) = out;
    }
}

// ---------------------------------------------------------------------------
// Persistent fp16 GEMM with register-level software pipelining.
// 296 CTAs (2/SM), 128 threads (2m x 2n warps => 64x64 tiles), CTA 128x128,
// BK=64, 3 smem stages, cp.async.wait_group 0 + one sync per chunk.
// bh ping-pong (next B frag loads during current MMAs); ah reloaded after
// last use; chunk c+1's first frags tail-prefetched during chunk c's tail
// (safe: wait0+sync at chunk top makes c+1's data globally visible).
// Static flat schedule: slot s runs tile j=s, then j=591-s if 80<=s<=295.
// ---------------------------------------------------------------------------
#define STAGE 32768
#define NSTAGE 3
#define SMEM_TOTAL (NSTAGE * STAGE)

__device__ __forceinline__ uint32_t a_addr(uint32_t base, int wm, int lane,
                                           int mf, int ks) {
    const int row = (wm << 6) + (mf << 4) + (lane & 15);
    const int ch = ((ks << 1) + (lane >> 4)) ^ (row & 7);
    return base + (row << 7) + (ch << 4);
}
__device__ __forceinline__ uint32_t b_addr(uint32_t base, int wn, int lane,
                                           int ng, int ks) {
    const int n = (wn << 6) + (ng << 4) + ((lane >> 4) << 3) + (lane & 7);
    const int ch = ((ks << 1) + ((lane >> 3) & 1)) ^ (n & 7);
    return base + 16384 + (n << 7) + (ch << 4);
}

__global__ __launch_bounds__(128, 2)
void gemm_mma(const float* __restrict__ bias, float* __restrict__ y) {
    extern __shared__ __align__(1024) char smem[];
    const uint32_t sb = smem_u32(smem);

    const int tid  = threadIdx.x;
    const int wid  = tid >> 5;
    const int lane = tid & 31;
    const int wm = wid >> 1;          // 0..1
    const int wn = wid & 1;           // 0..1

    const int s = blockIdx.x;         // persistent slot, 0..295
    const int ntiles = (s >= 80) ? 2 : 1;

    int j = s;
    int nt = 31 - (j >> 4);
    int mt = j & 15;
    int n0 = nt << 7;
    int m0 = mt << 7;
    int NC = (nt + 1) << 1;

    const __half* gA = g_xh + (size_t)m0 * K_IN;
    const __half* gB = g_wh + (size_t)n0 * K_IN;

    auto load_stage = [&](int st, int c) {
        const uint32_t base = sb + st * STAGE;
        const int k0 = c << 6;
        #pragma unroll
        for (int i = 0; i < 8; i++) {
            const int idx = tid + (i << 7);
            const int r = idx >> 3;
            const int ch = idx & 7;
            const size_t go = (size_t)r * K_IN + k0 + (ch << 3);
            const uint32_t so = (uint32_t)((r << 7) | ((ch ^ (r & 7)) << 4));
            cp16(base + so,         gA + go);
            cp16(base + 16384 + so, gB + go);
        }
    };

    // Tile-0 prologue: chunks 0,1 (NC >= 2 always).
    load_stage(0, 0);
    CP_COMMIT();
    load_stage(1, 1);
    CP_COMMIT();

    uint32_t ah[4][4];     // current A fragments (one ks-step)
    uint32_t bh[2][4];     // B fragment ping-pong

    for (int t = 0; t < ntiles; t++) {
        float acc[4][8][4];
        #pragma unroll
        for (int i = 0; i < 4; i++)
            #pragma unroll
            for (int jj = 0; jj < 8; jj++)
                #pragma unroll
                for (int k = 0; k < 4; k++) acc[i][jj][k] = 0.f;

        for (int c = 0; c < NC; ++c) {
            // All outstanding cp.async groups complete (at most chunk c+1's,
            // issued one full chunk ago), then make them globally visible and
            // free the stage that load_stage below will overwrite.
            CP_WAIT0();
            __syncthreads();

            const uint32_t bc = sb + (c % NSTAGE) * STAGE;
            const uint32_t bn = sb + ((c + 1) % NSTAGE) * STAGE;
            const bool hasnext = (c + 1 < NC);

            if (c == 0) {     // first chunk of tile: cold-load fragments
                #pragma unroll
                for (int mf = 0; mf < 4; mf++)
                    LDM4(ah[mf], a_addr(bc, wm, lane, mf, 0));
                LDM4(bh[0], b_addr(bc, wn, lane, 0, 0));
            }

            if (c + 2 < NC) {
                load_stage((c + 2) % NSTAGE, c + 2);
                CP_COMMIT();
            }

            #pragma unroll
            for (int ks = 0; ks < 4; ks++) {
                #pragma unroll
                for (int ng = 0; ng < 4; ng++) {
                    const int tp = ((ks << 2) + ng) & 1;   // current bh buffer
                    // Preload the NEXT B fragment into the other buffer.
                    if (!(ks == 3 && ng == 3)) {
                        const int nks = (ng == 3) ? ks + 1 : ks;
                        const int nng = (ng == 3) ? 0 : ng + 1;
                        LDM4(bh[tp ^ 1], b_addr(bc, wn, lane, nng, nks));
                    } else if (hasnext) {
                        LDM4(bh[0], b_addr(bn, wn, lane, 0, 0));
                    }
                    // 8 MMAs on the current fragments.
                    #pragma unroll
                    for (int mf = 0; mf < 4; mf++)
                        #pragma unroll
                        for (int h = 0; h < 2; h++)
                            MMAF16(acc[mf][(ng << 1) + h], ah[mf],
                                   bh[tp][2 * h], bh[tp][2 * h + 1]);
                    // Reload A fragments right after their last use.
                    if (ng == 3) {
                        if (ks < 3) {
                            #pragma unroll
                            for (int mf = 0; mf < 4; mf++)
                                LDM4(ah[mf], a_addr(bc, wm, lane, mf, ks + 1));
                        } else if (hasnext) {
                            #pragma unroll
                            for (int mf = 0; mf < 4; mf++)
                                LDM4(ah[mf], a_addr(bn, wm, lane, mf, 0));
                        }
                    }
                }
            }
        }

        const int m0_out = m0, n0_out = n0;

        __syncthreads();    // all warps done with this tile's smem
        if (t + 1 < ntiles) {
            j = 591 - s;
            nt = 31 - (j >> 4);
            mt = j & 15;
            n0 = nt << 7;
            m0 = mt << 7;
            NC = (nt + 1) << 1;
            gA = g_xh + (size_t)m0 * K_IN;
            gB = g_wh + (size_t)n0 * K_IN;
            load_stage(0, 0);      // next tile's prologue hides under epilogue
            CP_COMMIT();
            load_stage(1, 1);
            CP_COMMIT();
        }

        #pragma unroll
        for (int mf = 0; mf < 4; mf++) {
            const int r = m0_out + (wm << 6) + (mf << 4) + (lane >> 2);
            #pragma unroll
            for (int nf = 0; nf < 8; nf++) {
                const int cc = n0_out + (wn << 6) + (nf << 3) + ((lane & 3) << 1);
                const float b0 = __ldg(bias + cc);
                const float b1 = __ldg(bias + cc + 1);
                float2 v0 = { acc[mf][nf][0] + b0, acc[mf][nf][1] + b1 };
                float2 v1 = { acc[mf][nf][2] + b0, acc[mf][nf][3] + b1 };
                *(float2*)(y + (size_t)r * N_OUT + cc)       = v0;
                *(float2*)(y + (size_t)(r + 8) * N_OUT + cc) = v1;
            }
        }
    }
}

// ---------------------------------------------------------------------------
extern "C" void kernel_launch(void* const* d_in, const int* in_sizes, int n_in,
                              void* d_out, int out_size) {
    const float* x    = (const float*)d_in[0];
    const float* W    = (const float*)d_in[1];
    const float* bias = (const float*)d_in[2];
    const float* wls  = (const float*)d_in[3];
    // masks (d_in[4], d_in[5]) deterministic; never read.

    float* y   = (float*)d_out;
    float* jac = y + (size_t)M_BATCH * N_OUT;

    cudaFuncSetAttribute(gemm_mma, cudaFuncAttributeMaxDynamicSharedMemorySize,
                         SMEM_TOTAL);

    prep_all<<<8192, 256, (4096 + 256) * sizeof(float)>>>(x, W, wls, jac);
    gemm_mma<<<296, 128, SMEM_TOTAL>>>(bias, y);
}